// round 14
// baseline (speedup 1.0000x reference)
#include <cuda_runtime.h>
#include <cuda_fp16.h>
#include <math.h>
#include <stdint.h>

#define N_TOK 32768
#define C_DIM 256
#define E_NUM 16
#define NMAT 17
#define RBLK 512          // router blocks (64 tokens each)
#define NTASK 24          // 4 chunks x (5 triples + 1 double)

// ---------------- scratch (no allocations allowed) ----------------
__device__ float g_combine[N_TOK * E_NUM];
__device__ float g_pt[RBLK * 16];
__device__ float g_pp[RBLK * 16];
__device__ __align__(128) __half g_Whi[NMAT * C_DIM * C_DIM];

__device__ __forceinline__ uint32_t smem_u32(const void* p) {
    uint32_t a;
    asm("{ .reg .u64 t; cvta.to.shared.u64 t, %1; cvt.u32.u64 %0, t; }" : "=r"(a) : "l"(p));
    return a;
}

// ---------------- kernel 1: fused router + W-prep ----------------
__global__ __launch_bounds__(256) void prep_kernel(
    const float* __restrict__ conv, const float* __restrict__ emb,
    const float* __restrict__ gateW, const float* __restrict__ gateB,
    const float* __restrict__ gamma, const float* __restrict__ beta,
    const float* __restrict__ shareW, const float* __restrict__ expW)
{
    int tid = threadIdx.x;

    if (blockIdx.x >= RBLK) {
        // ---- W prep: transpose + fp16 convert ----
        __shared__ float tile[32][33];
        int w = blockIdx.x - RBLK;
        int m = w >> 6;
        int rr = w & 63;
        int by = rr >> 3, bx = rr & 7;
        const float* src = (m == 0) ? shareW : expW + (size_t)(m - 1) * 65536;
        int tx = tid & 31, ty = tid >> 5;
        if (ty < 8) {
#pragma unroll
            for (int i = 0; i < 4; i++) {
                int k = by * 32 + ty + i * 8;
                int n = bx * 32 + tx;
                tile[ty + i * 8][tx] = src[k * 256 + n];
            }
        }
        __syncthreads();
        if (ty < 8) {
#pragma unroll
            for (int i = 0; i < 4; i++) {
                int n = bx * 32 + ty + i * 8;
                int k = by * 32 + tx;
                float v = tile[tx][ty + i * 8];
                g_Whi[(size_t)m * 65536 + (size_t)n * 256 + k] = __float2half_rn(v);
            }
        }
        return;
    }

    // ---- router: 8 warps x 8 tokens, 4 tokens per e/j pass (2 pairs) ----
    __shared__ float gwT[16 * 257];
    __shared__ float gbev[3 * 256 + 16];
    __shared__ float wpt[8 * 16], wpp[8 * 16];
    for (int idx = tid; idx < 4096; idx += 256)
        gwT[(idx & 15) * 257 + (idx >> 4)] = gateW[idx];
    if (tid < 256) {
        gbev[tid] = gamma[tid];
        gbev[256 + tid] = beta[tid];
        gbev[512 + tid] = emb[tid];
    }
    if (tid < 16) gbev[768 + tid] = gateB[tid];
    __syncthreads();

    int warp = tid >> 5, lane = tid & 31;
    int half = lane >> 4;
    int sl = lane & 15;
    float st = 0.f, sp = 0.f;

#pragma unroll 1
    for (int i = 0; i < 2; i++) {
        int nb = blockIdx.x * 64 + warp * 8 + i * 4;
        int n0t = nb + half;
        int n1t = nb + 2 + half;
        const float* row0 = conv + (size_t)n0t * C_DIM;
        const float* row1 = conv + (size_t)n1t * C_DIM;

        float r0[16], r1[16];
        {
            float x0[16], x1[16];
            float s0 = 0.f, q0 = 0.f, s1 = 0.f, q1 = 0.f;
#pragma unroll
            for (int j = 0; j < 16; j++) {
                x0[j] = row0[sl + 16 * j];
                x1[j] = row1[sl + 16 * j];
                s0 += x0[j]; q0 += x0[j] * x0[j];
                s1 += x1[j]; q1 += x1[j] * x1[j];
            }
#pragma unroll
            for (int o = 8; o; o >>= 1) {
                s0 += __shfl_xor_sync(0xffffffffu, s0, o);
                q0 += __shfl_xor_sync(0xffffffffu, q0, o);
                s1 += __shfl_xor_sync(0xffffffffu, s1, o);
                q1 += __shfl_xor_sync(0xffffffffu, q1, o);
            }
            float mu0 = s0 * (1.f / 256.f);
            float rstd0 = rsqrtf(q0 * (1.f / 256.f) - mu0 * mu0 + 1e-5f);
            float mu1 = s1 * (1.f / 256.f);
            float rstd1 = rsqrtf(q1 * (1.f / 256.f) - mu1 * mu1 + 1e-5f);
#pragma unroll
            for (int j = 0; j < 16; j++) {
                int c = sl + 16 * j;
                float g = gbev[c], b = gbev[256 + c] + gbev[512 + c];
                r0[j] = (x0[j] - mu0) * rstd0 * g + b;
                r1[j] = (x1[j] - mu1) * rstd1 * g + b;
            }
        }

        float v0[16], v1[16];
#pragma unroll
        for (int e = 0; e < 16; e++) {
            float p0 = 0.f, p1 = 0.f;
#pragma unroll
            for (int j = 0; j < 16; j++) {
                float gw = gwT[e * 257 + sl + 16 * j];
                p0 += r0[j] * gw;
                p1 += r1[j] * gw;
            }
            v0[e] = p0; v1[e] = p1;
        }

#pragma unroll
        for (int step = 8; step >= 1; step >>= 1) {
            bool hi = (sl & step) != 0;
#pragma unroll
            for (int j = 0; j < 8; j++) {
                if (j < step) {
                    float k0 = hi ? v0[j + step] : v0[j];
                    float d0 = hi ? v0[j] : v0[j + step];
                    v0[j] = k0 + __shfl_xor_sync(0xffffffffu, d0, step);
                    float k1 = hi ? v1[j + step] : v1[j];
                    float d1 = hi ? v1[j] : v1[j + step];
                    v1[j] = k1 + __shfl_xor_sync(0xffffffffu, d1, step);
                }
            }
        }

#pragma unroll 1
        for (int tk = 0; tk < 2; tk++) {
            int n = tk ? n1t : n0t;
            float L = (tk ? v1[0] : v0[0]) + gbev[768 + sl];

            float a[16];
            a[0] = L;
            a[1] = __shfl_xor_sync(0xffffffffu, a[0], 1);
#pragma unroll
            for (int q = 0; q < 2; q++) a[2 + q] = __shfl_xor_sync(0xffffffffu, a[q], 2);
#pragma unroll
            for (int q = 0; q < 4; q++) a[4 + q] = __shfl_xor_sync(0xffffffffu, a[q], 4);
#pragma unroll
            for (int q = 0; q < 8; q++) a[8 + q] = __shfl_xor_sync(0xffffffffu, a[q], 8);

            float mx = a[0];
#pragma unroll
            for (int e = 1; e < 16; e++) mx = fmaxf(mx, a[e]);
            float sum = 0.f;
#pragma unroll
            for (int e = 0; e < 16; e++) { a[e] = expf(a[e] - mx); sum += a[e]; }
            float inv = 1.f / sum;
            float ent = 0.f;
#pragma unroll
            for (int e = 0; e < 16; e++) { a[e] *= inv; ent -= a[e] * logf(a[e] + 1e-12f); }
            float kf = ceilf(1.f + ent * (15.f / 2.7725887222397811f));
            int k = (int)kf; k = k < 1 ? 1 : (k > 16 ? 16 : k);

            float we = a[0];
            int rank = 0;
#pragma unroll
            for (int j = 1; j < 16; j++) {
                int ej = sl ^ j;
                rank += (a[j] > we) || (a[j] == we && ej < sl);
            }
            int sel = rank < k;
            g_combine[(size_t)n * 16 + sl] = sel ? we : 0.f;
            st += sel ? 1.f : 0.f;
            sp += we;
        }
    }

    st += __shfl_xor_sync(0xffffffffu, st, 16);
    sp += __shfl_xor_sync(0xffffffffu, sp, 16);
    if (lane < 16) { wpt[warp * 16 + lane] = st; wpp[warp * 16 + lane] = sp; }
    __syncthreads();
    if (tid < 16) {
        float t = 0.f, p = 0.f;
#pragma unroll
        for (int w = 0; w < 8; w++) { t += wpt[w * 16 + tid]; p += wpp[w * 16 + tid]; }
        g_pt[blockIdx.x * 16 + tid] = t;
        g_pp[blockIdx.x * 16 + tid] = p;
    }
}

// ---------------- kernel 2: mma.sync fused MoE GEMM v11 + fused loss ----------------
// CTA 128(M) x 64(N), 256 threads (8 warps 4x2, warp 32x32), 2 CTAs/SM.
// Three matrices per pipeline stage -> 24 sync windows.
#define WS_OFF 0            // 3 stages x 27648 (3 matrices x 64 rows x 144B)
#define XC_OFF 82944        // current X chunk (fp16): 128 rows x 144B = 18432
#define SC_OFF 101376       // [17][64] half2 pairs = 4352
#define BS_OFF 105728       // [17][64] f32 = 4352
#define SMEM_BYTES 110080

#define LDSM4(R, A) \
    asm volatile("ldmatrix.sync.aligned.m8n8.x4.shared.b16 {%0,%1,%2,%3}, [%4];" \
        : "=r"((R)[0]), "=r"((R)[1]), "=r"((R)[2]), "=r"((R)[3]) : "r"(A))
#define MMA16816(D, A, B) \
    asm volatile("mma.sync.aligned.m16n8k16.row.col.f32.f16.f16.f32 " \
        "{%0,%1,%2,%3}, {%4,%5,%6,%7}, {%8,%9}, {%0,%1,%2,%3};" \
        : "+f"((D)[0]), "+f"((D)[1]), "+f"((D)[2]), "+f"((D)[3]) \
        : "r"((A)[0]), "r"((A)[1]), "r"((A)[2]), "r"((A)[3]), "r"((B)[0]), "r"((B)[1]))

__device__ __forceinline__ uint32_t packh(float a, float b) {
    __half2 h = __floats2half2_rn(a, b);
    return *reinterpret_cast<uint32_t*>(&h);
}
__device__ __forceinline__ uint32_t hmul2u(uint32_t a, uint32_t b) {
    __half2 r = __hmul2(*reinterpret_cast<__half2*>(&a), *reinterpret_cast<__half2*>(&b));
    return *reinterpret_cast<uint32_t*>(&r);
}

// prefetch W for task t: chunk c = t/6, group g = t%6 (matrices 3g.. ; g==5: 2 mats)
__device__ __forceinline__ void prefetch_w(uint32_t wbase, int t, int colBase, int tid)
{
    const int c = t / 6;
    const int g = t - c * 6;
    const int stage = t % 3;
    const int mbase = 3 * g;
    const int nseg = (g == 5) ? 1024 : 1536;   // 16B segments (2 or 3 matrices)
#pragma unroll
    for (int i = 0; i < 6; i++) {
        int idx = tid + i * 256;           // 0..1535
        if (idx < nseg) {
            int mi = idx >> 9;             // matrix within group
            int r = (idx >> 3) & 63;       // n row 0..63
            int q = idx & 7;               // 16B segment along k
            const __half* src = g_Whi +
                (size_t)(mbase + mi) * 65536 + (size_t)(colBase + r) * 256 + c * 64 + q * 8;
            uint32_t dst = wbase + stage * 27648 + mi * 9216 + r * 144 + q * 16;
            asm volatile("cp.async.cg.shared.global [%0], [%1], 16;"
                         :: "r"(dst), "l"(src) : "memory");
        }
    }
    asm volatile("cp.async.commit_group;" ::: "memory");
}

// convert X chunk (128 rows x 64 k) from gmem to fp16 into XC buffer
__device__ __forceinline__ void convert_x(char* smc, const float* Xb, int chunk, int tid)
{
#pragma unroll
    for (int i = 0; i < 8; i++) {
        int idx = tid + i * 256;           // 0..2047 float4 slots
        int r = idx >> 4;                  // row 0..127
        int k4 = idx & 15;
        float4 v = reinterpret_cast<const float4*>(Xb + (size_t)r * 256 + chunk * 64)[k4];
        uint2 h = make_uint2(packh(v.x, v.y), packh(v.z, v.w));
        *reinterpret_cast<uint2*>(smc + XC_OFF + r * 144 + k4 * 8) = h;
    }
}

__global__ __launch_bounds__(256, 2) void moe_mma_kernel(
    const float* __restrict__ X,
    const float* __restrict__ shareB,
    const float* __restrict__ expB,
    float* __restrict__ out,
    int out_size)
{
    extern __shared__ char smc[];
    const int tid = threadIdx.x;
    const int lane = tid & 31, warp = tid >> 5;
    const int rowBase = blockIdx.y * 128;
    const int colBase = blockIdx.x * 64;
    const uint32_t sb = smem_u32(smc);
    const uint32_t wbase = sb + WS_OFF;

    prefetch_w(wbase, 0, colBase, tid);

    // ---- fused loss finalize (block (0,0) only) ----
    if (blockIdx.x == 0 && blockIdx.y == 0) {
        const int NC = N_TOK * C_DIM;
        if (tid < 16) {
            float t = 0.f, p = 0.f;
            for (int b = 0; b < RBLK; b++) {
                t += g_pt[b * 16 + tid];
                p += g_pp[b * 16 + tid];
            }
            float prod = (t * (1.f / (float)N_TOK)) * (p * (1.f / (float)N_TOK));
#pragma unroll
            for (int o = 8; o; o >>= 1) prod += __shfl_xor_sync(0xffffu, prod, o);
            if (tid == 0 && out_size > NC) out[NC] = prod * 16.f;
        }
        for (int i = NC + 1 + tid; i < out_size; i += 256)
            out[i] = 0.f;
    }

    __half2* Sc2 = reinterpret_cast<__half2*>(smc + SC_OFF);
    float* Bs = reinterpret_cast<float*>(smc + BS_OFF);

    for (int idx = tid; idx < 17 * 64; idx += 256) {
        int m = idx >> 6, j = idx & 63;
        int row = ((j >> 3) << 4) + (j & 7);
        float f0, f1;
        if (m == 0) { f0 = 1.0f; f1 = 1.0f; }
        else {
            f0 = g_combine[(size_t)(rowBase + row) * 16 + (m - 1)];
            f1 = g_combine[(size_t)(rowBase + row + 8) * 16 + (m - 1)];
        }
        Sc2[idx] = __floats2half2_rn(f0, f1);
    }
    for (int idx = tid; idx < 17 * 64; idx += 256) {
        int m = idx >> 6, c = idx & 63;
        Bs[idx] = (m == 0) ? shareB[colBase + c] : expB[(m - 1) * 256 + colBase + c];
    }

    prefetch_w(wbase, 1, colBase, tid);

    const float* Xb = X + (size_t)rowBase * 256;
    convert_x(smc, Xb, 0, tid);

    const int m0 = (warp & 3) * 32;
    const int n0 = (warp >> 2) * 32;

    const uint32_t xh_base = sb + XC_OFF + (uint32_t)(m0 + (lane & 15)) * 144 + (lane >> 4) * 16;
    const uint32_t wb_base = wbase +
        (uint32_t)(n0 + ((lane >> 4) & 1) * 8 + (lane & 7)) * 144 + ((lane >> 3) & 1) * 16;

    const int rq = lane >> 2;
    const int cq = (lane & 3) * 2;
    const int scBase = (warp & 3) * 16 + rq;

    float acc[2][4][4];
#pragma unroll
    for (int mt = 0; mt < 2; mt++)
#pragma unroll
        for (int nt = 0; nt < 4; nt++)
#pragma unroll
            for (int q = 0; q < 4; q++) acc[mt][nt][q] = 0.f;

    __syncthreads();   // X chunk 0 / Sc2 / Bs visible

    // acc init = sum_m s_m * b_m
#pragma unroll 1
    for (int m = 0; m < NMAT; m++) {
        float2 fa = __half22float2(Sc2[m * 64 + scBase]);
        float2 fb = __half22float2(Sc2[m * 64 + scBase + 8]);
#pragma unroll
        for (int nt = 0; nt < 4; nt++) {
            float b0 = Bs[m * 64 + n0 + nt * 8 + cq];
            float b1 = Bs[m * 64 + n0 + nt * 8 + cq + 1];
            acc[0][nt][0] += fa.x * b0; acc[0][nt][1] += fa.x * b1;
            acc[0][nt][2] += fa.y * b0; acc[0][nt][3] += fa.y * b1;
            acc[1][nt][0] += fb.x * b0; acc[1][nt][1] += fb.x * b1;
            acc[1][nt][2] += fb.y * b0; acc[1][nt][3] += fb.y * b1;
        }
    }

    uint32_t Ah[4][2][4];

#pragma unroll 1
    for (int t = 0; t < NTASK; t++) {
        const int c = t / 6;
        const int g = t - c * 6;
        const int stage = t % 3;
        const int mbase = 3 * g;
        const int nm = (g == 5) ? 2 : 3;

        asm volatile("cp.async.wait_group 1;" ::: "memory");
        __syncthreads();

        if (g == 0) {
#pragma unroll
            for (int ks = 0; ks < 4; ks++) {
#pragma unroll
                for (int mt = 0; mt < 2; mt++)
                    LDSM4(Ah[ks][mt], xh_base + mt * (16 * 144) + ks * 32);
            }
        }
        if (g == 1 && c < 3) {
            convert_x(smc, Xb, c + 1, tid);
        }

#pragma unroll 1
        for (int mi = 0; mi < nm; mi++) {
            const int m = mbase + mi;
            __half2 h2a = Sc2[m * 64 + scBase];
            __half2 h2b = Sc2[m * 64 + scBase + 8];
            uint32_t sA0, sA1, sB0, sB1;
            {
                __half2 t0 = __half2half2(__low2half(h2a));
                __half2 t1 = __half2half2(__high2half(h2a));
                __half2 t2 = __half2half2(__low2half(h2b));
                __half2 t3 = __half2half2(__high2half(h2b));
                sA0 = *reinterpret_cast<uint32_t*>(&t0);
                sA1 = *reinterpret_cast<uint32_t*>(&t1);
                sB0 = *reinterpret_cast<uint32_t*>(&t2);
                sB1 = *reinterpret_cast<uint32_t*>(&t3);
            }

            const uint32_t wbs = wb_base + stage * 27648 + mi * 9216;
#pragma unroll
            for (int ks = 0; ks < 4; ks++) {
                uint32_t Bh[4][2];
#pragma unroll
                for (int ntp = 0; ntp < 2; ntp++) {
                    uint32_t r4[4];
                    LDSM4(r4, wbs + ntp * (16 * 144) + ks * 32);
                    Bh[ntp * 2][0] = r4[0]; Bh[ntp * 2][1] = r4[1];
                    Bh[ntp * 2 + 1][0] = r4[2]; Bh[ntp * 2 + 1][1] = r4[3];
                }
                uint32_t As[4];
                As[0] = hmul2u(Ah[ks][0][0], sA0);
                As[1] = hmul2u(Ah[ks][0][1], sA1);
                As[2] = hmul2u(Ah[ks][0][2], sA0);
                As[3] = hmul2u(Ah[ks][0][3], sA1);
#pragma unroll
                for (int nt = 0; nt < 4; nt++)
                    MMA16816(acc[0][nt], As, Bh[nt]);
                As[0] = hmul2u(Ah[ks][1][0], sB0);
                As[1] = hmul2u(Ah[ks][1][1], sB1);
                As[2] = hmul2u(Ah[ks][1][2], sB0);
                As[3] = hmul2u(Ah[ks][1][3], sB1);
#pragma unroll
                for (int nt = 0; nt < 4; nt++)
                    MMA16816(acc[1][nt], As, Bh[nt]);
            }
        }

        if (t + 2 < NTASK) prefetch_w(wbase, t + 2, colBase, tid);
        else asm volatile("cp.async.commit_group;" ::: "memory");
    }

    // write output
#pragma unroll
    for (int mt = 0; mt < 2; mt++) {
        int rg = rowBase + m0 + mt * 16 + rq;
#pragma unroll
        for (int nt = 0; nt < 4; nt++) {
            int cg = colBase + n0 + nt * 8 + cq;
            *reinterpret_cast<float2*>(out + (size_t)rg * 256 + cg) =
                make_float2(acc[mt][nt][0], acc[mt][nt][1]);
            *reinterpret_cast<float2*>(out + (size_t)(rg + 8) * 256 + cg) =
                make_float2(acc[mt][nt][2], acc[mt][nt][3]);
        }
    }
}

// ---------------- launch ----------------
extern "C" void kernel_launch(void* const* d_in, const int* in_sizes, int n_in,
                              void* d_out, int out_size)
{
    const float* inputs = (const float*)d_in[0];
    const float* conv   = (const float*)d_in[1];
    const float* emb    = (const float*)d_in[2];
    const float* shareW = (const float*)d_in[3];
    const float* shareB = (const float*)d_in[4];
    const float* gateW  = (const float*)d_in[5];
    const float* gateB  = (const float*)d_in[6];
    const float* expW   = (const float*)d_in[7];
    const float* expB   = (const float*)d_in[8];
    const float* gamma  = (const float*)d_in[9];
    const float* beta   = (const float*)d_in[10];
    float* out = (float*)d_out;

    prep_kernel<<<RBLK + NMAT * 64, 256>>>(conv, emb, gateW, gateB, gamma, beta,
                                           shareW, expW);

    cudaFuncSetAttribute(moe_mma_kernel,
                         cudaFuncAttributeMaxDynamicSharedMemorySize, SMEM_BYTES);
    moe_mma_kernel<<<dim3(4, 256), 256, SMEM_BYTES>>>(inputs, shareB, expB, out,
                                                      out_size);
}